// round 3
// baseline (speedup 1.0000x reference)
#include <cuda_runtime.h>
#include <cuda_fp16.h>

#define Bn 4
#define Sn 256
#define Hn 160
#define NHn 8
#define HDn 20
#define FFn 640
#define MAXLENn 512
#define TBLn 1025
#define BSn (Bn*Sn)
#define R2 8
#define TR 16
#define TBLOCKS 65   // ceil(1025/16)

// ------------------------- device scratch (static, no allocs) ----------------
__device__ uint2 dPh4[4 * TBLn * (Hn / 4)];  // fused pe tables fp16 (rows = 40 uint2 = 160 half)
__device__ float dKT[Bn * Hn * Sn];          // K transposed: [b][hd][j]
__device__ float dV[BSn * Hn];
__device__ float dQU[BSn * Hn];              // q + u
__device__ float dG[BSn * NHn * Hn];         // g[b,i,h,c]
__device__ float dATT[BSn * Hn];
__device__ float dY1[BSn * Hn];
__device__ float dH1[BSn * FFn];

__device__ __forceinline__ void ffma2(unsigned long long& d, unsigned long long a,
                                      unsigned long long b) {
    asm("fma.rn.f32x2 %0, %1, %2, %3;" : "=l"(d) : "l"(a), "l"(b), "l"(d));
}
__device__ __forceinline__ __half2 u2h(unsigned x) {
    return *reinterpret_cast<__half2*>(&x);
}

// ------------------------- K1: P_t = pe_t @ W_fus[t] (+ b_fus for t=0), fp16 out
// One launch handles 2 tables: t = t0 + blockIdx.x/TBLOCKS.
__global__ void k_tables(const float* __restrict__ pe_a, const float* __restrict__ pe_b,
                         const float* __restrict__ W_fus, const float* __restrict__ b_fus,
                         int t0) {
    int sel = blockIdx.x / TBLOCKS;
    int t = t0 + sel;
    int r0 = (blockIdx.x % TBLOCKS) * TR;
    const float* pe = sel ? pe_b : pe_a;
    __shared__ float rows[TR][Hn];
    int c = threadIdx.x;
#pragma unroll
    for (int r = 0; r < TR; r++) {
        int rr = r0 + r;
        rows[r][c] = (rr < TBLn) ? pe[rr * Hn + c] : 0.f;
    }
    __syncthreads();
    float bias = (t == 0) ? b_fus[c] : 0.f;
    float acc[TR];
#pragma unroll
    for (int r = 0; r < TR; r++) acc[r] = bias;
    const float* wf = W_fus + t * Hn * Hn;
    for (int k = 0; k < Hn; k++) {
        float w = wf[k * Hn + c];
#pragma unroll
        for (int r = 0; r < TR; r++) acc[r] += rows[r][k] * w;
    }
    __half* out = (__half*)dPh4;
#pragma unroll
    for (int r = 0; r < TR; r++) {
        int rr = r0 + r;
        if (rr < TBLn) out[(size_t)(t * TBLn + rr) * Hn + c] = __float2half(acc[r]);
    }
}

// ------------------------- K2: q/k/v projections + g (Wr read directly) -----
__global__ void k_qkvg(const float* __restrict__ inp,
                       const float* __restrict__ Wq, const float* __restrict__ bq,
                       const float* __restrict__ Wk, const float* __restrict__ bk,
                       const float* __restrict__ Wv, const float* __restrict__ bv,
                       const float* __restrict__ Wr,
                       const float* __restrict__ u, const float* __restrict__ v) {
    int row0 = blockIdx.x * R2;
    int b = row0 >> 8;
    int i0 = row0 & 255;
    int c = threadIdx.x;
    __shared__ float xs[R2][Hn];
    __shared__ float qv[R2][Hn];
#pragma unroll
    for (int r = 0; r < R2; r++) xs[r][c] = inp[(row0 + r) * Hn + c];
    __syncthreads();

    float acc[R2];
    // Q
#pragma unroll
    for (int r = 0; r < R2; r++) acc[r] = bq[c];
    for (int k = 0; k < Hn; k++) {
        float w = Wq[k * Hn + c];
#pragma unroll
        for (int r = 0; r < R2; r++) acc[r] += xs[r][k] * w;
    }
    {
        float uu = u[c], vv = v[c];
#pragma unroll
        for (int r = 0; r < R2; r++) {
            dQU[(row0 + r) * Hn + c] = acc[r] + uu;
            qv[r][c] = acc[r] + vv;
        }
    }
    // K -> transposed store
#pragma unroll
    for (int r = 0; r < R2; r++) acc[r] = bk[c];
    for (int k = 0; k < Hn; k++) {
        float w = Wk[k * Hn + c];
#pragma unroll
        for (int r = 0; r < R2; r++) acc[r] += xs[r][k] * w;
    }
#pragma unroll
    for (int r = 0; r < R2; r++) dKT[((size_t)b * Hn + c) * Sn + (i0 + r)] = acc[r];
    // V
#pragma unroll
    for (int r = 0; r < R2; r++) acc[r] = bv[c];
    for (int k = 0; k < Hn; k++) {
        float w = Wv[k * Hn + c];
#pragma unroll
        for (int r = 0; r < R2; r++) acc[r] += xs[r][k] * w;
    }
#pragma unroll
    for (int r = 0; r < R2; r++) dV[(row0 + r) * Hn + c] = acc[r];
    __syncthreads();

    // g[b,i,h,c] = sum_hd qv[hd] * Wr[c*Hn + hd]   (row c of Wr, contiguous)
    const float4* wr4 = reinterpret_cast<const float4*>(Wr + (size_t)c * Hn);
    for (int h = 0; h < NHn; h++) {
        float a2[R2];
#pragma unroll
        for (int r = 0; r < R2; r++) a2[r] = 0.f;
#pragma unroll
        for (int d4 = 0; d4 < 5; d4++) {
            float4 w4 = wr4[h * 5 + d4];
            int hd = h * HDn + d4 * 4;
#pragma unroll
            for (int r = 0; r < R2; r++) {
                a2[r] += qv[r][hd + 0] * w4.x + qv[r][hd + 1] * w4.y +
                         qv[r][hd + 2] * w4.z + qv[r][hd + 3] * w4.w;
            }
        }
#pragma unroll
        for (int r = 0; r < R2; r++) dG[((size_t)(row0 + r) * NHn + h) * Hn + c] = a2[r];
    }
}

// ------------------------- K3: fused A_C + rel-gather/B_D + softmax + attn@V -
__global__ void __launch_bounds__(256) k_attn(const int* __restrict__ pos_s,
                                              const int* __restrict__ pos_e,
                                              const int* __restrict__ seq_len,
                                              const int* __restrict__ lex) {
    int b = blockIdx.x >> 8;
    int i = blockIdx.x & 255;
    int tid = threadIdx.x;
    int lane = tid & 31;
    int w = tid >> 5;
    int l8 = lane & 7;
    int q8 = lane >> 3;

    __shared__ float sc[NHn][257];
    __shared__ int pssO[Sn], pesO[Sn];
    __shared__ float quv[Hn];
    __shared__ __align__(16) float g_s[NHn * Hn];
    __shared__ float rinv[NHn];
    __shared__ int psi_s, pei_s;

    {
        int ps = pos_s[b * Sn + tid];
        int pe = pos_e[b * Sn + tid];
        pssO[tid] = ps * 40;
        pesO[tid] = pe * 40;
        if (tid == i) { psi_s = ps; pei_s = pe; }
    }
    if (tid < Hn) quv[tid] = dQU[(size_t)(b * Sn + i) * Hn + tid];
    {
        const float* gp = dG + (size_t)(b * Sn + i) * NHn * Hn;
        for (int t = tid; t < NHn * Hn; t += 256) g_s[t] = gp[t];
    }
    __syncthreads();

    // ---- Phase AC: sc[h][j] = sum_d qu[h,d] * K[b,j,h,d], coalesced via dKT
    {
        float acc[NHn];
#pragma unroll
        for (int h = 0; h < NHn; h++) acc[h] = 0.f;
#pragma unroll
        for (int h = 0; h < NHn; h++) {
            const float* kp = dKT + ((size_t)b * Hn + h * HDn) * Sn + tid;
#pragma unroll
            for (int d = 0; d < HDn; d++) acc[h] += quv[h * HDn + d] * kp[(size_t)d * Sn];
        }
#pragma unroll
        for (int h = 0; h < NHn; h++) sc[h][tid] = acc[h];
    }
    __syncthreads();

    // ---- Phase BD
    int psi = psi_s + MAXLENn;
    int pei = pei_s + MAXLENn;
    const uint2* base0 = dPh4 + (size_t)(0 * TBLn + psi) * 40 + l8;
    const uint2* base1 = dPh4 + (size_t)(1 * TBLn + psi) * 40 + l8;
    const uint2* base2 = dPh4 + (size_t)(2 * TBLn + pei) * 40 + l8;
    const uint2* base3 = dPh4 + (size_t)(3 * TBLn + pei) * 40 + l8;
    const __half2 hz = __float2half2_rn(0.f);

#pragma unroll 1
    for (int s = 0; s < 8; s++) {
        int j = (w << 5) + (s << 2) + q8;
        int offS = pssO[j], offE = pesO[j];
        const uint2* r0 = base0 - offS;
        const uint2* r1 = base1 - offE;
        const uint2* r2 = base2 - offS;
        const uint2* r3 = base3 - offE;
        unsigned long long acc2[NHn];
#pragma unroll
        for (int h = 0; h < NHn; h++) acc2[h] = 0ull;
#pragma unroll
        for (int cc = 0; cc < 5; cc++) {
            uint2 a0 = r0[cc * 8], a1 = r1[cc * 8], a2 = r2[cc * 8], a3 = r3[cc * 8];
            __half2 sx = __hmax2(__hadd2(__hadd2(u2h(a0.x), u2h(a1.x)),
                                         __hadd2(u2h(a2.x), u2h(a3.x))), hz);
            __half2 sy = __hmax2(__hadd2(__hadd2(u2h(a0.y), u2h(a1.y)),
                                         __hadd2(u2h(a2.y), u2h(a3.y))), hz);
            float2 fx = __half22float2(sx);
            float2 fy = __half22float2(sy);
            unsigned long long relA, relB;
            asm("mov.b64 %0, {%1,%2};" : "=l"(relA) : "f"(fx.x), "f"(fx.y));
            asm("mov.b64 %0, {%1,%2};" : "=l"(relB) : "f"(fy.x), "f"(fy.y));
#pragma unroll
            for (int h = 0; h < NHn; h++) {
                const ulonglong2* gp = reinterpret_cast<const ulonglong2*>(g_s + h * Hn);
                ulonglong2 gg = gp[cc * 8 + l8];
                ffma2(acc2[h], relA, gg.x);
                ffma2(acc2[h], relB, gg.y);
            }
        }
        float a[NHn];
#pragma unroll
        for (int h = 0; h < NHn; h++) {
            float lo, hi;
            asm("mov.b64 {%0,%1}, %2;" : "=f"(lo), "=f"(hi) : "l"(acc2[h]));
            a[h] = lo + hi;
        }
        // reduce-scatter over the 8-lane group: lane l8 ends with head l8
        {
            bool hb = (l8 & 4);
#pragma unroll
            for (int k = 0; k < 4; k++) {
                float send = hb ? a[k] : a[k + 4];
                float got = __shfl_xor_sync(0xffffffffu, send, 4);
                a[k] = (hb ? a[k + 4] : a[k]) + got;
            }
        }
        {
            bool hb = (l8 & 2);
#pragma unroll
            for (int k = 0; k < 2; k++) {
                float send = hb ? a[k] : a[k + 2];
                float got = __shfl_xor_sync(0xffffffffu, send, 2);
                a[k] = (hb ? a[k + 2] : a[k]) + got;
            }
        }
        {
            bool hb = (l8 & 1);
            float send = hb ? a[0] : a[1];
            float got = __shfl_xor_sync(0xffffffffu, send, 1);
            a[0] = (hb ? a[1] : a[0]) + got;
        }
        sc[l8][j] += a[0];
    }
    __syncthreads();

    // ---- scale + mask
    {
        int lim = seq_len[b] + lex[0];
        bool valid = tid < lim;
        const float scale = 0.223606797749979f;
#pragma unroll
        for (int h = 0; h < NHn; h++) {
            float sv = sc[h][tid] * scale;
            sc[h][tid] = valid ? sv : -1e15f;
        }
    }
    __syncthreads();

    // ---- per-head softmax (warp w = head w); unnormalized p + 1/sum
    {
        int h = w;
        float m = -1e30f;
#pragma unroll
        for (int q = 0; q < 8; q++) m = fmaxf(m, sc[h][lane + q * 32]);
#pragma unroll
        for (int off = 16; off; off >>= 1) m = fmaxf(m, __shfl_xor_sync(0xffffffffu, m, off));
        float ssum = 0.f;
#pragma unroll
        for (int q = 0; q < 8; q++) {
            float p = __expf(sc[h][lane + q * 32] - m);
            sc[h][lane + q * 32] = p;
            ssum += p;
        }
#pragma unroll
        for (int off = 16; off; off >>= 1) ssum += __shfl_xor_sync(0xffffffffu, ssum, off);
        if (lane == 0) rinv[h] = 1.0f / ssum;
    }
    __syncthreads();

    // ---- out[c] = (sum_j p[h][j] * V[b,j,c]) * rinv[h]
    if (tid < Hn) {
        int c = tid;
        int h = c / HDn;
        const float* vp = dV + (size_t)b * Sn * Hn + c;
        float acc = 0.f;
#pragma unroll 8
        for (int j = 0; j < Sn; j++) acc += sc[h][j] * vp[(size_t)j * Hn];
        dATT[((size_t)b * Sn + i) * Hn + c] = acc * rinv[h];
    }
}

// ------------------------- K4: @W_fin + b_fin, x2, LN1 ----------------------
__global__ void k_fin_ln(const float* __restrict__ W_fin, const float* __restrict__ b_fin,
                         const float* __restrict__ g1, const float* __restrict__ be1) {
    int row0 = blockIdx.x * R2;
    int c = threadIdx.x;
    int lane = c & 31, w = c >> 5;
    __shared__ float xs[R2][Hn];
    __shared__ float ys[R2][Hn];
    __shared__ float part1[5], part2[5];
    __shared__ float mu_s, rs_s;
#pragma unroll
    for (int r = 0; r < R2; r++) xs[r][c] = dATT[(row0 + r) * Hn + c];
    __syncthreads();
    float acc[R2];
#pragma unroll
    for (int r = 0; r < R2; r++) acc[r] = b_fin[c];
    for (int k = 0; k < Hn; k++) {
        float ww = W_fin[k * Hn + c];
#pragma unroll
        for (int r = 0; r < R2; r++) acc[r] += xs[r][k] * ww;
    }
#pragma unroll
    for (int r = 0; r < R2; r++) ys[r][c] = 2.f * acc[r];
    __syncthreads();
    for (int r = 0; r < R2; r++) {
        float v = ys[r][c];
        float s1 = v, s2 = v * v;
#pragma unroll
        for (int off = 16; off; off >>= 1) {
            s1 += __shfl_xor_sync(0xffffffffu, s1, off);
            s2 += __shfl_xor_sync(0xffffffffu, s2, off);
        }
        if (lane == 0) { part1[w] = s1; part2[w] = s2; }
        __syncthreads();
        if (c == 0) {
            float a = 0.f, q = 0.f;
#pragma unroll
            for (int t = 0; t < 5; t++) { a += part1[t]; q += part2[t]; }
            float mu = a / Hn;
            mu_s = mu;
            rs_s = rsqrtf(q / Hn - mu * mu + 1e-5f);
        }
        __syncthreads();
        dY1[(row0 + r) * Hn + c] = (v - mu_s) * rs_s * g1[c] + be1[c];
        __syncthreads();
    }
}

// ------------------------- K5: FFN1 = relu(y1 @ W1 + b1), col-split ---------
__global__ void k_ffn1(const float* __restrict__ W1, const float* __restrict__ b1) {
    int rb = blockIdx.x >> 1;
    int half = blockIdx.x & 1;
    int row0 = rb * R2;
    int t = threadIdx.x;  // 320
    int c = half * 320 + t;
    __shared__ float xs[R2 * Hn];
    for (int q = t; q < R2 * Hn; q += 320) xs[q] = dY1[row0 * Hn + q];
    __syncthreads();
    float a0[R2];
#pragma unroll
    for (int r = 0; r < R2; r++) a0[r] = b1[c];
    for (int k = 0; k < Hn; k++) {
        float w0 = W1[k * FFn + c];
#pragma unroll
        for (int r = 0; r < R2; r++) a0[r] += xs[r * Hn + k] * w0;
    }
#pragma unroll
    for (int r = 0; r < R2; r++) dH1[(row0 + r) * FFn + c] = fmaxf(a0[r], 0.f);
}

// ------------------------- K6: FFN2 + b2, x2, LN2 -> out (split-k x2) -------
__global__ void k_ffn2_ln(const float* __restrict__ W2, const float* __restrict__ b2,
                          const float* __restrict__ g2, const float* __restrict__ be2,
                          float* __restrict__ out) {
    int row0 = blockIdx.x * R2;
    int tid = threadIdx.x;  // 320
    int kh = (tid >= Hn) ? 1 : 0;
    int c = tid - kh * Hn;
    int lane = tid & 31, w = tid >> 5;
    __shared__ float hs[R2 * FFn];
    __shared__ float psum[R2][Hn];
    __shared__ float ys[R2][Hn];
    __shared__ float part1[5], part2[5];
    __shared__ float mu_s, rs_s;
    for (int q = tid; q < R2 * FFn; q += 320) hs[q] = dH1[row0 * FFn + q];
    __syncthreads();
    float acc[R2];
#pragma unroll
    for (int r = 0; r < R2; r++) acc[r] = kh ? 0.f : b2[c];
    int kbase = kh * 320;
    for (int k = 0; k < 320; k++) {
        float ww = W2[(kbase + k) * Hn + c];
#pragma unroll
        for (int r = 0; r < R2; r++) acc[r] += hs[r * FFn + kbase + k] * ww;
    }
    if (kh) {
#pragma unroll
        for (int r = 0; r < R2; r++) psum[r][c] = acc[r];
    }
    __syncthreads();
    if (!kh) {
#pragma unroll
        for (int r = 0; r < R2; r++) ys[r][c] = 2.f * (acc[r] + psum[r][c]);
    }
    __syncthreads();
    for (int r = 0; r < R2; r++) {
        float v = (tid < Hn) ? ys[r][c] : 0.f;
        float s1 = v, s2 = v * v;
#pragma unroll
        for (int off = 16; off; off >>= 1) {
            s1 += __shfl_xor_sync(0xffffffffu, s1, off);
            s2 += __shfl_xor_sync(0xffffffffu, s2, off);
        }
        if (lane == 0 && w < 5) { part1[w] = s1; part2[w] = s2; }
        __syncthreads();
        if (tid == 0) {
            float a = 0.f, q = 0.f;
#pragma unroll
            for (int t = 0; t < 5; t++) { a += part1[t]; q += part2[t]; }
            float mu = a / Hn;
            mu_s = mu;
            rs_s = rsqrtf(q / Hn - mu * mu + 1e-5f);
        }
        __syncthreads();
        if (tid < Hn) out[(row0 + r) * Hn + c] = (ys[r][c] - mu_s) * rs_s * g2[c] + be2[c];
        __syncthreads();
    }
}

// ------------------------- launch -------------------------------------------
extern "C" void kernel_launch(void* const* d_in, const int* in_sizes, int n_in,
                              void* d_out, int out_size) {
    const float* inp   = (const float*)d_in[0];
    const int* pos_s   = (const int*)d_in[1];
    const int* pos_e   = (const int*)d_in[2];
    const int* seq_len = (const int*)d_in[3];
    const int* lex     = (const int*)d_in[4];
    const float* pe_ss = (const float*)d_in[5];
    const float* pe_se = (const float*)d_in[6];
    const float* pe_es = (const float*)d_in[7];
    const float* pe_ee = (const float*)d_in[8];
    const float* W_fus = (const float*)d_in[9];
    const float* b_fus = (const float*)d_in[10];
    const float* Wq    = (const float*)d_in[11];
    const float* bq    = (const float*)d_in[12];
    const float* Wk    = (const float*)d_in[13];
    const float* bk    = (const float*)d_in[14];
    const float* Wv    = (const float*)d_in[15];
    const float* bv    = (const float*)d_in[16];
    const float* Wr    = (const float*)d_in[17];
    // d_in[18] = br: constant over j inside softmax -> cancels exactly, unused
    const float* u     = (const float*)d_in[19];
    const float* v     = (const float*)d_in[20];
    const float* W_fin = (const float*)d_in[21];
    const float* b_fin = (const float*)d_in[22];
    const float* ln1_g = (const float*)d_in[23];
    const float* ln1_b = (const float*)d_in[24];
    const float* W1    = (const float*)d_in[25];
    const float* b1    = (const float*)d_in[26];
    const float* W2    = (const float*)d_in[27];
    const float* b2    = (const float*)d_in[28];
    const float* ln2_g = (const float*)d_in[29];
    const float* ln2_b = (const float*)d_in[30];

    k_tables<<<2 * TBLOCKS, Hn>>>(pe_ss, pe_se, W_fus, b_fus, 0);   // launch 1
    k_tables<<<2 * TBLOCKS, Hn>>>(pe_es, pe_ee, W_fus, b_fus, 2);   // launch 2
    k_qkvg<<<BSn / R2, Hn>>>(inp, Wq, bq, Wk, bk, Wv, bv, Wr, u, v); // launch 3
    k_attn<<<BSn, 256>>>(pos_s, pos_e, seq_len, lex);               // launch 4 (profiled slot)
    k_fin_ln<<<BSn / R2, Hn>>>(W_fin, b_fin, ln1_g, ln1_b);
    k_ffn1<<<(BSn / R2) * 2, 320>>>(W1, b1);
    k_ffn2_ln<<<BSn / R2, 320>>>(W2, b2, ln2_g, ln2_b, (float*)d_out);
}

// round 4
// speedup vs baseline: 1.0814x; 1.0814x over previous
#include <cuda_runtime.h>
#include <cuda_fp16.h>

#define Bn 4
#define Sn 256
#define Hn 160
#define NHn 8
#define HDn 20
#define FFn 640
#define MAXLENn 512
#define TBLn 1025
#define BSn (Bn*Sn)
#define R2 8
#define TR 16
#define TBLOCKS 65   // ceil(1025/16)

// ------------------------- device scratch (static, no allocs) ----------------
__device__ uint4 dPT[4 * TBLn * 20];   // fused pe tables fp16 (row = 20 uint4 = 160 half)
__device__ float dKT[Bn * Hn * Sn];    // K transposed: [b][hd][j]
__device__ float dV[BSn * Hn];
__device__ float dQU[BSn * Hn];        // q + u
__device__ float dG[BSn * NHn * Hn];   // g[b,i,h,c]
__device__ float dATT[BSn * Hn];
__device__ float dY1[BSn * Hn];
__device__ float dH1[BSn * FFn];

__device__ __forceinline__ void ffma2(unsigned long long& d, unsigned long long a,
                                      unsigned long long b) {
    asm("fma.rn.f32x2 %0, %1, %2, %3;" : "=l"(d) : "l"(a), "l"(b), "l"(d));
}
__device__ __forceinline__ __half2 u2h(unsigned x) {
    return *reinterpret_cast<__half2*>(&x);
}
__device__ __forceinline__ unsigned long long packf2(float2 f) {
    unsigned long long r;
    asm("mov.b64 %0, {%1,%2};" : "=l"(r) : "f"(f.x), "f"(f.y));
    return r;
}

// ------------------------- K1: P_t = pe_t @ W_fus[t] (+ b_fus for t=0), fp16 out
__global__ void k_tables(const float* __restrict__ pe_a, const float* __restrict__ pe_b,
                         const float* __restrict__ W_fus, const float* __restrict__ b_fus,
                         int t0) {
    int sel = blockIdx.x / TBLOCKS;
    int t = t0 + sel;
    int r0 = (blockIdx.x % TBLOCKS) * TR;
    const float* pe = sel ? pe_b : pe_a;
    __shared__ float rows[TR][Hn];
    int c = threadIdx.x;
#pragma unroll
    for (int r = 0; r < TR; r++) {
        int rr = r0 + r;
        rows[r][c] = (rr < TBLn) ? pe[rr * Hn + c] : 0.f;
    }
    __syncthreads();
    float bias = (t == 0) ? b_fus[c] : 0.f;
    float acc[TR];
#pragma unroll
    for (int r = 0; r < TR; r++) acc[r] = bias;
    const float* wf = W_fus + t * Hn * Hn;
    for (int k = 0; k < Hn; k++) {
        float w = wf[k * Hn + c];
#pragma unroll
        for (int r = 0; r < TR; r++) acc[r] += rows[r][k] * w;
    }
    __half* out = (__half*)dPT;
#pragma unroll
    for (int r = 0; r < TR; r++) {
        int rr = r0 + r;
        if (rr < TBLn) out[(size_t)(t * TBLn + rr) * Hn + c] = __float2half(acc[r]);
    }
}

// ------------------------- K2: q/k/v projections + g ------------------------
__global__ void k_qkvg(const float* __restrict__ inp,
                       const float* __restrict__ Wq, const float* __restrict__ bq,
                       const float* __restrict__ Wk, const float* __restrict__ bk,
                       const float* __restrict__ Wv, const float* __restrict__ bv,
                       const float* __restrict__ Wr,
                       const float* __restrict__ u, const float* __restrict__ v) {
    int row0 = blockIdx.x * R2;
    int b = row0 >> 8;
    int i0 = row0 & 255;
    int c = threadIdx.x;
    __shared__ float xs[R2][Hn];
    __shared__ float qv[R2][Hn];
#pragma unroll
    for (int r = 0; r < R2; r++) xs[r][c] = inp[(row0 + r) * Hn + c];
    __syncthreads();

    float acc[R2];
#pragma unroll
    for (int r = 0; r < R2; r++) acc[r] = bq[c];
    for (int k = 0; k < Hn; k++) {
        float w = Wq[k * Hn + c];
#pragma unroll
        for (int r = 0; r < R2; r++) acc[r] += xs[r][k] * w;
    }
    {
        float uu = u[c], vv = v[c];
#pragma unroll
        for (int r = 0; r < R2; r++) {
            dQU[(row0 + r) * Hn + c] = acc[r] + uu;
            qv[r][c] = acc[r] + vv;
        }
    }
#pragma unroll
    for (int r = 0; r < R2; r++) acc[r] = bk[c];
    for (int k = 0; k < Hn; k++) {
        float w = Wk[k * Hn + c];
#pragma unroll
        for (int r = 0; r < R2; r++) acc[r] += xs[r][k] * w;
    }
#pragma unroll
    for (int r = 0; r < R2; r++) dKT[((size_t)b * Hn + c) * Sn + (i0 + r)] = acc[r];
#pragma unroll
    for (int r = 0; r < R2; r++) acc[r] = bv[c];
    for (int k = 0; k < Hn; k++) {
        float w = Wv[k * Hn + c];
#pragma unroll
        for (int r = 0; r < R2; r++) acc[r] += xs[r][k] * w;
    }
#pragma unroll
    for (int r = 0; r < R2; r++) dV[(row0 + r) * Hn + c] = acc[r];
    __syncthreads();

    const float4* wr4 = reinterpret_cast<const float4*>(Wr + (size_t)c * Hn);
    for (int h = 0; h < NHn; h++) {
        float a2[R2];
#pragma unroll
        for (int r = 0; r < R2; r++) a2[r] = 0.f;
#pragma unroll
        for (int d4 = 0; d4 < 5; d4++) {
            float4 w4 = wr4[h * 5 + d4];
            int hd = h * HDn + d4 * 4;
#pragma unroll
            for (int r = 0; r < R2; r++) {
                a2[r] += qv[r][hd + 0] * w4.x + qv[r][hd + 1] * w4.y +
                         qv[r][hd + 2] * w4.z + qv[r][hd + 3] * w4.w;
            }
        }
#pragma unroll
        for (int r = 0; r < R2; r++) dG[((size_t)(row0 + r) * NHn + h) * Hn + c] = a2[r];
    }
}

// ------------------------- K3: fused A_C + B_D + softmax + attn@V -----------
// thread tid owns key index j = tid entirely (no cross-lane reductions).
__global__ void __launch_bounds__(256, 2) k_attn(const int* __restrict__ pos_s,
                                                 const int* __restrict__ pos_e,
                                                 const int* __restrict__ seq_len,
                                                 const int* __restrict__ lex) {
    int b = blockIdx.x >> 8;
    int i = blockIdx.x & 255;
    int tid = threadIdx.x;
    int lane = tid & 31;
    int w = tid >> 5;

    __shared__ float sc[NHn][257];
    __shared__ int pssO[Sn], pesO[Sn];   // pos * 20 (uint4 row units)
    __shared__ float quv[Hn];
    __shared__ __align__(16) float g_s[NHn * Hn];
    __shared__ float rinv[NHn];
    __shared__ int psi_s, pei_s, lim_s;

    {
        int ps = pos_s[b * Sn + tid];
        int pe = pos_e[b * Sn + tid];
        pssO[tid] = ps * 20;
        pesO[tid] = pe * 20;
        if (tid == i) { psi_s = ps; pei_s = pe; }
        if (tid == 0) lim_s = seq_len[b] + lex[0];
    }
    if (tid < Hn) quv[tid] = dQU[(size_t)(b * Sn + i) * Hn + tid];
    {
        const float* gp = dG + (size_t)(b * Sn + i) * NHn * Hn;
        for (int t = tid; t < NHn * Hn; t += 256) g_s[t] = gp[t];
    }
    __syncthreads();

    int lim = lim_s;

    // ---- Phase AC (unscaled); invalid j get final -1e15
    if (tid < lim) {
        float acc[NHn];
#pragma unroll
        for (int h = 0; h < NHn; h++) acc[h] = 0.f;
#pragma unroll
        for (int h = 0; h < NHn; h++) {
            const float* kp = dKT + ((size_t)b * Hn + h * HDn) * Sn + tid;
#pragma unroll
            for (int d = 0; d < HDn; d++) acc[h] += quv[h * HDn + d] * kp[(size_t)d * Sn];
        }
#pragma unroll
        for (int h = 0; h < NHn; h++) sc[h][tid] = acc[h];
    } else {
#pragma unroll
        for (int h = 0; h < NHn; h++) sc[h][tid] = -1e15f;
    }

    // ---- Phase BD: gather 4 fp16 rows, relu, dot with g (broadcast smem)
    if (tid < lim) {
        const uint4* r0 = dPT + (size_t)(0 * TBLn + psi_s + MAXLENn) * 20 - pssO[tid];
        const uint4* r1 = dPT + (size_t)(1 * TBLn + psi_s + MAXLENn) * 20 - pesO[tid];
        const uint4* r2 = dPT + (size_t)(2 * TBLn + pei_s + MAXLENn) * 20 - pssO[tid];
        const uint4* r3 = dPT + (size_t)(3 * TBLn + pei_s + MAXLENn) * 20 - pesO[tid];
        const __half2 hz = __float2half2_rn(0.f);
        unsigned long long acc2[NHn];
#pragma unroll
        for (int h = 0; h < NHn; h++) acc2[h] = 0ull;
#pragma unroll 2
        for (int gi = 0; gi < 20; gi++) {
            uint4 a0 = r0[gi], a1 = r1[gi], a2 = r2[gi], a3 = r3[gi];
            __half2 h01 = __hmax2(__hadd2(__hadd2(u2h(a0.x), u2h(a1.x)),
                                          __hadd2(u2h(a2.x), u2h(a3.x))), hz);
            __half2 h23 = __hmax2(__hadd2(__hadd2(u2h(a0.y), u2h(a1.y)),
                                          __hadd2(u2h(a2.y), u2h(a3.y))), hz);
            __half2 h45 = __hmax2(__hadd2(__hadd2(u2h(a0.z), u2h(a1.z)),
                                          __hadd2(u2h(a2.z), u2h(a3.z))), hz);
            __half2 h67 = __hmax2(__hadd2(__hadd2(u2h(a0.w), u2h(a1.w)),
                                          __hadd2(u2h(a2.w), u2h(a3.w))), hz);
            unsigned long long rel01 = packf2(__half22float2(h01));
            unsigned long long rel23 = packf2(__half22float2(h23));
            unsigned long long rel45 = packf2(__half22float2(h45));
            unsigned long long rel67 = packf2(__half22float2(h67));
#pragma unroll
            for (int h = 0; h < NHn; h++) {
                const ulonglong2* gg =
                    reinterpret_cast<const ulonglong2*>(g_s + h * Hn + gi * 8);
                ulonglong2 gA = gg[0];
                ulonglong2 gB = gg[1];
                ffma2(acc2[h], rel01, gA.x);
                ffma2(acc2[h], rel23, gA.y);
                ffma2(acc2[h], rel45, gB.x);
                ffma2(acc2[h], rel67, gB.y);
            }
        }
        const float scale = 0.223606797749979f;
#pragma unroll
        for (int h = 0; h < NHn; h++) {
            float lo, hi;
            asm("mov.b64 {%0,%1}, %2;" : "=f"(lo), "=f"(hi) : "l"(acc2[h]));
            sc[h][tid] = (sc[h][tid] + lo + hi) * scale;
        }
    }
    __syncthreads();

    // ---- per-head softmax (warp w = head w); unnormalized p + 1/sum
    {
        int h = w;
        float m = -1e30f;
#pragma unroll
        for (int q = 0; q < 8; q++) m = fmaxf(m, sc[h][lane + q * 32]);
#pragma unroll
        for (int off = 16; off; off >>= 1) m = fmaxf(m, __shfl_xor_sync(0xffffffffu, m, off));
        float ssum = 0.f;
#pragma unroll
        for (int q = 0; q < 8; q++) {
            float p = __expf(sc[h][lane + q * 32] - m);
            sc[h][lane + q * 32] = p;
            ssum += p;
        }
#pragma unroll
        for (int off = 16; off; off >>= 1) ssum += __shfl_xor_sync(0xffffffffu, ssum, off);
        if (lane == 0) rinv[h] = 1.0f / ssum;
    }
    __syncthreads();

    // ---- out[c] = (sum_j p[h][j] * V[b,j,c]) * rinv[h]
    if (tid < Hn) {
        int c = tid;
        int h = c / HDn;
        const float* vp = dV + (size_t)b * Sn * Hn + c;
        float acc = 0.f;
#pragma unroll 8
        for (int j = 0; j < Sn; j++) acc += sc[h][j] * vp[(size_t)j * Hn];
        dATT[((size_t)b * Sn + i) * Hn + c] = acc * rinv[h];
    }
}

// ------------------------- K4: @W_fin + b_fin, x2, LN1 ----------------------
__global__ void k_fin_ln(const float* __restrict__ W_fin, const float* __restrict__ b_fin,
                         const float* __restrict__ g1, const float* __restrict__ be1) {
    int row0 = blockIdx.x * R2;
    int c = threadIdx.x;
    int lane = c & 31, w = c >> 5;
    __shared__ float xs[R2][Hn];
    __shared__ float ys[R2][Hn];
    __shared__ float part1[5], part2[5];
    __shared__ float mu_s, rs_s;
#pragma unroll
    for (int r = 0; r < R2; r++) xs[r][c] = dATT[(row0 + r) * Hn + c];
    __syncthreads();
    float acc[R2];
#pragma unroll
    for (int r = 0; r < R2; r++) acc[r] = b_fin[c];
    for (int k = 0; k < Hn; k++) {
        float ww = W_fin[k * Hn + c];
#pragma unroll
        for (int r = 0; r < R2; r++) acc[r] += xs[r][k] * ww;
    }
#pragma unroll
    for (int r = 0; r < R2; r++) ys[r][c] = 2.f * acc[r];
    __syncthreads();
    for (int r = 0; r < R2; r++) {
        float v = ys[r][c];
        float s1 = v, s2 = v * v;
#pragma unroll
        for (int off = 16; off; off >>= 1) {
            s1 += __shfl_xor_sync(0xffffffffu, s1, off);
            s2 += __shfl_xor_sync(0xffffffffu, s2, off);
        }
        if (lane == 0) { part1[w] = s1; part2[w] = s2; }
        __syncthreads();
        if (c == 0) {
            float a = 0.f, q = 0.f;
#pragma unroll
            for (int t = 0; t < 5; t++) { a += part1[t]; q += part2[t]; }
            float mu = a / Hn;
            mu_s = mu;
            rs_s = rsqrtf(q / Hn - mu * mu + 1e-5f);
        }
        __syncthreads();
        dY1[(row0 + r) * Hn + c] = (v - mu_s) * rs_s * g1[c] + be1[c];
        __syncthreads();
    }
}

// ------------------------- K5: FFN1 = relu(y1 @ W1 + b1), col-split ---------
__global__ void k_ffn1(const float* __restrict__ W1, const float* __restrict__ b1) {
    int rb = blockIdx.x >> 1;
    int half = blockIdx.x & 1;
    int row0 = rb * R2;
    int t = threadIdx.x;  // 320
    int c = half * 320 + t;
    __shared__ float xs[R2 * Hn];
    for (int q = t; q < R2 * Hn; q += 320) xs[q] = dY1[row0 * Hn + q];
    __syncthreads();
    float a0[R2];
#pragma unroll
    for (int r = 0; r < R2; r++) a0[r] = b1[c];
    for (int k = 0; k < Hn; k++) {
        float w0 = W1[k * FFn + c];
#pragma unroll
        for (int r = 0; r < R2; r++) a0[r] += xs[r * Hn + k] * w0;
    }
#pragma unroll
    for (int r = 0; r < R2; r++) dH1[(row0 + r) * FFn + c] = fmaxf(a0[r], 0.f);
}

// ------------------------- K6: FFN2 + b2, x2, LN2 -> out (split-k x2) -------
__global__ void k_ffn2_ln(const float* __restrict__ W2, const float* __restrict__ b2,
                          const float* __restrict__ g2, const float* __restrict__ be2,
                          float* __restrict__ out) {
    int row0 = blockIdx.x * R2;
    int tid = threadIdx.x;  // 320
    int kh = (tid >= Hn) ? 1 : 0;
    int c = tid - kh * Hn;
    int lane = tid & 31, w = tid >> 5;
    __shared__ float hs[R2 * FFn];
    __shared__ float psum[R2][Hn];
    __shared__ float ys[R2][Hn];
    __shared__ float part1[5], part2[5];
    __shared__ float mu_s, rs_s;
    for (int q = tid; q < R2 * FFn; q += 320) hs[q] = dH1[row0 * FFn + q];
    __syncthreads();
    float acc[R2];
#pragma unroll
    for (int r = 0; r < R2; r++) acc[r] = kh ? 0.f : b2[c];
    int kbase = kh * 320;
    for (int k = 0; k < 320; k++) {
        float ww = W2[(kbase + k) * Hn + c];
#pragma unroll
        for (int r = 0; r < R2; r++) acc[r] += hs[r * FFn + kbase + k] * ww;
    }
    if (kh) {
#pragma unroll
        for (int r = 0; r < R2; r++) psum[r][c] = acc[r];
    }
    __syncthreads();
    if (!kh) {
#pragma unroll
        for (int r = 0; r < R2; r++) ys[r][c] = 2.f * (acc[r] + psum[r][c]);
    }
    __syncthreads();
    for (int r = 0; r < R2; r++) {
        float v = (tid < Hn) ? ys[r][c] : 0.f;
        float s1 = v, s2 = v * v;
#pragma unroll
        for (int off = 16; off; off >>= 1) {
            s1 += __shfl_xor_sync(0xffffffffu, s1, off);
            s2 += __shfl_xor_sync(0xffffffffu, s2, off);
        }
        if (lane == 0 && w < 5) { part1[w] = s1; part2[w] = s2; }
        __syncthreads();
        if (tid == 0) {
            float a = 0.f, q = 0.f;
#pragma unroll
            for (int t = 0; t < 5; t++) { a += part1[t]; q += part2[t]; }
            float mu = a / Hn;
            mu_s = mu;
            rs_s = rsqrtf(q / Hn - mu * mu + 1e-5f);
        }
        __syncthreads();
        if (tid < Hn) out[(row0 + r) * Hn + c] = (ys[r][c] - mu_s) * rs_s * g2[c] + be2[c];
        __syncthreads();
    }
}

// ------------------------- launch -------------------------------------------
extern "C" void kernel_launch(void* const* d_in, const int* in_sizes, int n_in,
                              void* d_out, int out_size) {
    const float* inp   = (const float*)d_in[0];
    const int* pos_s   = (const int*)d_in[1];
    const int* pos_e   = (const int*)d_in[2];
    const int* seq_len = (const int*)d_in[3];
    const int* lex     = (const int*)d_in[4];
    const float* pe_ss = (const float*)d_in[5];
    const float* pe_se = (const float*)d_in[6];
    const float* pe_es = (const float*)d_in[7];
    const float* pe_ee = (const float*)d_in[8];
    const float* W_fus = (const float*)d_in[9];
    const float* b_fus = (const float*)d_in[10];
    const float* Wq    = (const float*)d_in[11];
    const float* bq    = (const float*)d_in[12];
    const float* Wk    = (const float*)d_in[13];
    const float* bk    = (const float*)d_in[14];
    const float* Wv    = (const float*)d_in[15];
    const float* bv    = (const float*)d_in[16];
    const float* Wr    = (const float*)d_in[17];
    // d_in[18] = br: constant over j inside softmax -> cancels exactly, unused
    const float* u     = (const float*)d_in[19];
    const float* v     = (const float*)d_in[20];
    const float* W_fin = (const float*)d_in[21];
    const float* b_fin = (const float*)d_in[22];
    const float* ln1_g = (const float*)d_in[23];
    const float* ln1_b = (const float*)d_in[24];
    const float* W1    = (const float*)d_in[25];
    const float* b1    = (const float*)d_in[26];
    const float* W2    = (const float*)d_in[27];
    const float* b2    = (const float*)d_in[28];
    const float* ln2_g = (const float*)d_in[29];
    const float* ln2_b = (const float*)d_in[30];

    k_tables<<<2 * TBLOCKS, Hn>>>(pe_ss, pe_se, W_fus, b_fus, 0);    // launch 1
    k_tables<<<2 * TBLOCKS, Hn>>>(pe_es, pe_ee, W_fus, b_fus, 2);    // launch 2
    k_qkvg<<<BSn / R2, Hn>>>(inp, Wq, bq, Wk, bk, Wv, bv, Wr, u, v); // launch 3
    k_attn<<<BSn, 256>>>(pos_s, pos_e, seq_len, lex);                // launch 4 (profiled slot)
    k_fin_ln<<<BSn / R2, Hn>>>(W_fin, b_fin, ln1_g, ln1_b);
    k_ffn1<<<(BSn / R2) * 2, 320>>>(W1, b1);
    k_ffn2_ln<<<BSn / R2, 320>>>(W2, b2, ln2_g, ln2_b, (float*)d_out);
}

// round 6
// speedup vs baseline: 1.1369x; 1.0513x over previous
#include <cuda_runtime.h>
#include <cuda_fp16.h>

#define Bn 4
#define Sn 256
#define Hn 160
#define NHn 8
#define HDn 20
#define FFn 640
#define MAXLENn 512
#define TBLn 1025
#define BSn (Bn*Sn)
#define R2 8
#define TR 16
#define TBLOCKS 65     // ceil(1025/16)
#define RPAD 24        // uint4 per table row (20 data + 4 pad -> 384B, 128B aligned)
#define RSTR 80        // rel_s row stride in floats (320B: 16B-aligned, conflict-free)

// ------------------------- device scratch (static, no allocs) ----------------
__device__ uint4 dPT[4 * TBLn * RPAD];  // fused pe tables fp16, 384B padded rows
__device__ float dKT[Bn * Hn * Sn];     // K transposed: [b][hd][j]
__device__ float dV[BSn * Hn];
__device__ float dQU[BSn * Hn];         // q + u
__device__ float dG[BSn * NHn * Hn];    // g[b,i,h,c]
__device__ float dATT[BSn * Hn];
__device__ float dY1[BSn * Hn];
__device__ float dH1[BSn * FFn];

__device__ __forceinline__ void ffma2(unsigned long long& d, unsigned long long a,
                                      unsigned long long b) {
    asm("fma.rn.f32x2 %0, %1, %2, %3;" : "=l"(d) : "l"(a), "l"(b), "l"(d));
}
__device__ __forceinline__ __half2 u2h(unsigned x) {
    return *reinterpret_cast<__half2*>(&x);
}
__device__ __forceinline__ unsigned long long packf2(float2 f) {
    unsigned long long r;
    asm("mov.b64 %0, {%1,%2};" : "=l"(r) : "f"(f.x), "f"(f.y));
    return r;
}
__device__ __forceinline__ unsigned sum4relu(unsigned a, unsigned b, unsigned c,
                                             unsigned d, __half2 hz) {
    __half2 s = __hmax2(__hadd2(__hadd2(u2h(a), u2h(b)), __hadd2(u2h(c), u2h(d))), hz);
    return *reinterpret_cast<unsigned*>(&s);
}

// ------------------------- K1: P_t = pe_t @ W_fus[t] (+ b_fus for t=0), fp16 out
__global__ void k_tables(const float* __restrict__ pe_ss, const float* __restrict__ pe_se,
                         const float* __restrict__ pe_es, const float* __restrict__ pe_ee,
                         const float* __restrict__ W_fus, const float* __restrict__ b_fus) {
    int t = blockIdx.x / TBLOCKS;
    int r0 = (blockIdx.x % TBLOCKS) * TR;
    const float* pe = (t == 0) ? pe_ss : (t == 1) ? pe_se : (t == 2) ? pe_es : pe_ee;
    __shared__ float rows[TR][Hn];
    int c = threadIdx.x;
#pragma unroll
    for (int r = 0; r < TR; r++) {
        int rr = r0 + r;
        rows[r][c] = (rr < TBLn) ? pe[rr * Hn + c] : 0.f;
    }
    __syncthreads();
    float bias = (t == 0) ? b_fus[c] : 0.f;
    float acc[TR];
#pragma unroll
    for (int r = 0; r < TR; r++) acc[r] = bias;
    const float* wf = W_fus + t * Hn * Hn;
    for (int k = 0; k < Hn; k++) {
        float w = wf[k * Hn + c];
#pragma unroll
        for (int r = 0; r < TR; r++) acc[r] += rows[r][k] * w;
    }
    __half* out = (__half*)dPT;
#pragma unroll
    for (int r = 0; r < TR; r++) {
        int rr = r0 + r;
        if (rr < TBLn) out[(size_t)(t * TBLn + rr) * (RPAD * 8) + c] = __float2half(acc[r]);
    }
}

// ------------------------- K2: q/k/v projections + g ------------------------
__global__ void k_qkvg(const float* __restrict__ inp,
                       const float* __restrict__ Wq, const float* __restrict__ bq,
                       const float* __restrict__ Wk, const float* __restrict__ bk,
                       const float* __restrict__ Wv, const float* __restrict__ bv,
                       const float* __restrict__ Wr,
                       const float* __restrict__ u, const float* __restrict__ v) {
    int row0 = blockIdx.x * R2;
    int b = row0 >> 8;
    int i0 = row0 & 255;
    int c = threadIdx.x;
    __shared__ float xs[R2][Hn];
    __shared__ float qv[R2][Hn];
#pragma unroll
    for (int r = 0; r < R2; r++) xs[r][c] = inp[(row0 + r) * Hn + c];
    __syncthreads();

    float acc[R2];
#pragma unroll
    for (int r = 0; r < R2; r++) acc[r] = bq[c];
    for (int k = 0; k < Hn; k++) {
        float w = Wq[k * Hn + c];
#pragma unroll
        for (int r = 0; r < R2; r++) acc[r] += xs[r][k] * w;
    }
    {
        float uu = u[c], vv = v[c];
#pragma unroll
        for (int r = 0; r < R2; r++) {
            dQU[(row0 + r) * Hn + c] = acc[r] + uu;
            qv[r][c] = acc[r] + vv;
        }
    }
#pragma unroll
    for (int r = 0; r < R2; r++) acc[r] = bk[c];
    for (int k = 0; k < Hn; k++) {
        float w = Wk[k * Hn + c];
#pragma unroll
        for (int r = 0; r < R2; r++) acc[r] += xs[r][k] * w;
    }
#pragma unroll
    for (int r = 0; r < R2; r++) dKT[((size_t)b * Hn + c) * Sn + (i0 + r)] = acc[r];
#pragma unroll
    for (int r = 0; r < R2; r++) acc[r] = bv[c];
    for (int k = 0; k < Hn; k++) {
        float w = Wv[k * Hn + c];
#pragma unroll
        for (int r = 0; r < R2; r++) acc[r] += xs[r][k] * w;
    }
#pragma unroll
    for (int r = 0; r < R2; r++) dV[(row0 + r) * Hn + c] = acc[r];
    __syncthreads();

    const float4* wr4 = reinterpret_cast<const float4*>(Wr + (size_t)c * Hn);
    for (int h = 0; h < NHn; h++) {
        float a2[R2];
#pragma unroll
        for (int r = 0; r < R2; r++) a2[r] = 0.f;
#pragma unroll
        for (int d4 = 0; d4 < 5; d4++) {
            float4 w4 = wr4[h * 5 + d4];
            int hd = h * HDn + d4 * 4;
#pragma unroll
            for (int r = 0; r < R2; r++) {
                a2[r] += qv[r][hd + 0] * w4.x + qv[r][hd + 1] * w4.y +
                         qv[r][hd + 2] * w4.z + qv[r][hd + 3] * w4.w;
            }
        }
#pragma unroll
        for (int r = 0; r < R2; r++) dG[((size_t)(row0 + r) * NHn + h) * Hn + c] = a2[r];
    }
}

// ------------------------- K3: fused A_C + staged B_D + softmax + attn@V ----
__global__ void __launch_bounds__(256, 2) k_attn(const int* __restrict__ pos_s,
                                                 const int* __restrict__ pos_e,
                                                 const int* __restrict__ seq_len,
                                                 const int* __restrict__ lex) {
    int b = blockIdx.x >> 8;
    int i = blockIdx.x & 255;
    int tid = threadIdx.x;
    int lane = tid & 31;
    int w = tid >> 5;

    __shared__ float sc[NHn][257];
    __shared__ int pssO[Sn], pesO[Sn];    // pos * RPAD (uint4 units)
    __shared__ float quv[Hn];
    __shared__ __align__(16) float g_s[NHn * Hn];
    __shared__ float rinv[NHn];
    __shared__ __align__(16) float rel_s[64 * RSTR];  // fp16 rel rows
    __shared__ int psi_s, pei_s, lim_s;

    {
        int ps = pos_s[b * Sn + tid];
        int pe = pos_e[b * Sn + tid];
        pssO[tid] = ps * RPAD;
        pesO[tid] = pe * RPAD;
        if (tid == i) { psi_s = ps; pei_s = pe; }
        if (tid == 0) lim_s = seq_len[b] + lex[0];
    }
    if (tid < Hn) quv[tid] = dQU[(size_t)(b * Sn + i) * Hn + tid];
    {
        const float* gp = dG + (size_t)(b * Sn + i) * NHn * Hn;
        for (int t = tid; t < NHn * Hn; t += 256) g_s[t] = gp[t];
    }
    __syncthreads();

    int lim = lim_s;

    // ---- Phase AC (unscaled); invalid j get -1e15
    if (tid < lim) {
        float acc[NHn];
#pragma unroll
        for (int h = 0; h < NHn; h++) acc[h] = 0.f;
#pragma unroll
        for (int h = 0; h < NHn; h++) {
            const float* kp = dKT + ((size_t)b * Hn + h * HDn) * Sn + tid;
#pragma unroll
            for (int d = 0; d < HDn; d++) acc[h] += quv[h * HDn + d] * kp[(size_t)d * Sn];
        }
#pragma unroll
        for (int h = 0; h < NHn; h++) sc[h][tid] = acc[h];
    } else {
#pragma unroll
        for (int h = 0; h < NHn; h++) sc[h][tid] = -1e15f;
    }

    // ---- Phase BD: 4 chunks of 64 j; stage fp16 rel in smem, then 4-lane dot
    const uint4* base0 = dPT + (size_t)(0 * TBLn + psi_s + MAXLENn) * RPAD;
    const uint4* base1 = dPT + (size_t)(1 * TBLn + psi_s + MAXLENn) * RPAD;
    const uint4* base2 = dPT + (size_t)(2 * TBLn + pei_s + MAXLENn) * RPAD;
    const uint4* base3 = dPT + (size_t)(3 * TBLn + pei_s + MAXLENn) * RPAD;
    const __half2 hz = __float2half2_rn(0.f);
    int slot3 = tid >> 3;     // 0..31
    int l8 = tid & 7;
    int grp = lane >> 2;      // 0..7
    int l4 = lane & 3;
    const float scale = 0.223606797749979f;  // 1/sqrt(20)

#pragma unroll 1
    for (int chunk = 0; chunk < 4; chunk++) {
        int j0 = chunk * 64;
        __syncthreads();  // previous chunk's compute reads done
        // stage: 8 lanes per j, 2 passes of 32 j
#pragma unroll
        for (int p = 0; p < 2; p++) {
            int jj = slot3 + p * 32;
            int j = j0 + jj;
            if (j < lim) {
                int oS = pssO[j], oE = pesO[j];
                const uint4* r0 = base0 - oS;
                const uint4* r1 = base1 - oE;
                const uint4* r2 = base2 - oS;
                const uint4* r3 = base3 - oE;
#pragma unroll
                for (int m = 0; m < 3; m++) {
                    int k = l8 + 8 * m;
                    if (k < 20) {
                        uint4 a0 = r0[k], a1 = r1[k], a2 = r2[k], a3 = r3[k];
                        uint4 o;
                        o.x = sum4relu(a0.x, a1.x, a2.x, a3.x, hz);
                        o.y = sum4relu(a0.y, a1.y, a2.y, a3.y, hz);
                        o.z = sum4relu(a0.z, a1.z, a2.z, a3.z, hz);
                        o.w = sum4relu(a0.w, a1.w, a2.w, a3.w, hz);
                        *reinterpret_cast<uint4*>(rel_s + jj * RSTR + k * 4) = o;
                    }
                }
            }
        }
        __syncthreads();
        // compute: warp w handles j = j0 + w*8 + grp; lane l4 covers gi = l4+4m
        int jj = w * 8 + grp;
        int j = j0 + jj;
        unsigned long long acc2[NHn];
#pragma unroll
        for (int h = 0; h < NHn; h++) acc2[h] = 0ull;
        const float* rb = rel_s + jj * RSTR;
#pragma unroll
        for (int m = 0; m < 5; m++) {
            int k = l4 + 4 * m;
            uint4 rv = *reinterpret_cast<const uint4*>(rb + k * 4);
            unsigned long long rel01 = packf2(__half22float2(u2h(rv.x)));
            unsigned long long rel23 = packf2(__half22float2(u2h(rv.y)));
            unsigned long long rel45 = packf2(__half22float2(u2h(rv.z)));
            unsigned long long rel67 = packf2(__half22float2(u2h(rv.w)));
#pragma unroll
            for (int h = 0; h < NHn; h++) {
                const ulonglong2* gg =
                    reinterpret_cast<const ulonglong2*>(g_s + h * Hn + k * 8);
                ulonglong2 gA = gg[0];
                ulonglong2 gB = gg[1];
                ffma2(acc2[h], rel01, gA.x);
                ffma2(acc2[h], rel23, gA.y);
                ffma2(acc2[h], rel45, gB.x);
                ffma2(acc2[h], rel67, gB.y);
            }
        }
        float a[NHn];
#pragma unroll
        for (int h = 0; h < NHn; h++) {
            float lo, hi;
            asm("mov.b64 {%0,%1}, %2;" : "=f"(lo), "=f"(hi) : "l"(acc2[h]));
            a[h] = lo + hi;
        }
        // reduce-scatter over 4-lane group: lane l4 ends with heads {hbase, hbase+1}
        {
            bool hb = l4 & 1;
#pragma unroll
            for (int k2 = 0; k2 < 4; k2++) {
                float send = hb ? a[k2] : a[k2 + 4];
                float got = __shfl_xor_sync(0xffffffffu, send, 1);
                a[k2] = (hb ? a[k2 + 4] : a[k2]) + got;
            }
        }
        {
            bool hb = l4 & 2;
#pragma unroll
            for (int k2 = 0; k2 < 2; k2++) {
                float send = hb ? a[k2] : a[k2 + 2];
                float got = __shfl_xor_sync(0xffffffffu, send, 2);
                a[k2] = (hb ? a[k2 + 2] : a[k2]) + got;
            }
        }
        if (j < lim) {
            int hbase = (l4 & 1) * 4 + (l4 & 2);
            sc[hbase][j] += a[0];
            sc[hbase + 1][j] += a[1];
        }
    }
    __syncthreads();

    // ---- scale + mask
    {
        bool valid = tid < lim;
#pragma unroll
        for (int h = 0; h < NHn; h++) {
            float sv = sc[h][tid] * scale;
            sc[h][tid] = valid ? sv : -1e15f;
        }
    }
    __syncthreads();

    // ---- per-head softmax (warp w = head w); unnormalized p + 1/sum
    {
        int h = w;
        float m = -1e30f;
#pragma unroll
        for (int q = 0; q < 8; q++) m = fmaxf(m, sc[h][lane + q * 32]);
#pragma unroll
        for (int off = 16; off; off >>= 1) m = fmaxf(m, __shfl_xor_sync(0xffffffffu, m, off));
        float ssum = 0.f;
#pragma unroll
        for (int q = 0; q < 8; q++) {
            float p = __expf(sc[h][lane + q * 32] - m);
            sc[h][lane + q * 32] = p;
            ssum += p;
        }
#pragma unroll
        for (int off = 16; off; off >>= 1) ssum += __shfl_xor_sync(0xffffffffu, ssum, off);
        if (lane == 0) rinv[h] = 1.0f / ssum;
    }
    __syncthreads();

    // ---- out[c] = (sum_j p[h][j] * V[b,j,c]) * rinv[h]
    if (tid < Hn) {
        int c = tid;
        int h = c / HDn;
        const float* vp = dV + (size_t)b * Sn * Hn + c;
        float acc = 0.f;
#pragma unroll 8
        for (int j = 0; j < Sn; j++) acc += sc[h][j] * vp[(size_t)j * Hn];
        dATT[((size_t)b * Sn + i) * Hn + c] = acc * rinv[h];
    }
}

// ------------------------- K4: @W_fin + b_fin, x2, LN1 (R=4) ----------------
#define R2F 4
__global__ void k_fin_ln(const float* __restrict__ W_fin, const float* __restrict__ b_fin,
                         const float* __restrict__ g1, const float* __restrict__ be1) {
    int row0 = blockIdx.x * R2F;
    int c = threadIdx.x;
    int lane = c & 31, w = c >> 5;
    __shared__ float xs[R2F][Hn];
    __shared__ float ys[R2F][Hn];
    __shared__ float part1[5], part2[5];
    __shared__ float mu_s, rs_s;
#pragma unroll
    for (int r = 0; r < R2F; r++) xs[r][c] = dATT[(row0 + r) * Hn + c];
    __syncthreads();
    float acc[R2F];
#pragma unroll
    for (int r = 0; r < R2F; r++) acc[r] = b_fin[c];
    for (int k = 0; k < Hn; k++) {
        float ww = W_fin[k * Hn + c];
#pragma unroll
        for (int r = 0; r < R2F; r++) acc[r] += xs[r][k] * ww;
    }
#pragma unroll
    for (int r = 0; r < R2F; r++) ys[r][c] = 2.f * acc[r];
    __syncthreads();
    for (int r = 0; r < R2F; r++) {
        float v = ys[r][c];
        float s1 = v, s2 = v * v;
#pragma unroll
        for (int off = 16; off; off >>= 1) {
            s1 += __shfl_xor_sync(0xffffffffu, s1, off);
            s2 += __shfl_xor_sync(0xffffffffu, s2, off);
        }
        if (lane == 0) { part1[w] = s1; part2[w] = s2; }
        __syncthreads();
        if (c == 0) {
            float a = 0.f, q = 0.f;
#pragma unroll
            for (int t = 0; t < 5; t++) { a += part1[t]; q += part2[t]; }
            float mu = a / Hn;
            mu_s = mu;
            rs_s = rsqrtf(q / Hn - mu * mu + 1e-5f);
        }
        __syncthreads();
        dY1[(row0 + r) * Hn + c] = (v - mu_s) * rs_s * g1[c] + be1[c];
        __syncthreads();
    }
}

// ------------------------- K5: FFN1 = relu(y1 @ W1 + b1), 16-row x col-half --
#define RF1 16
__global__ void k_ffn1(const float* __restrict__ W1, const float* __restrict__ b1) {
    int rb = blockIdx.x >> 1;
    int half = blockIdx.x & 1;
    int row0 = rb * RF1;
    int t = threadIdx.x;  // 320
    int c = half * 320 + t;
    __shared__ float xs[RF1 * Hn];
    for (int q = t; q < RF1 * Hn; q += 320) xs[q] = dY1[row0 * Hn + q];
    __syncthreads();
    float a0[RF1];
#pragma unroll
    for (int r = 0; r < RF1; r++) a0[r] = b1[c];
    for (int k = 0; k < Hn; k++) {
        float w0 = W1[k * FFn + c];
#pragma unroll
        for (int r = 0; r < RF1; r++) a0[r] += xs[r * Hn + k] * w0;
    }
#pragma unroll
    for (int r = 0; r < RF1; r++) dH1[(row0 + r) * FFn + c] = fmaxf(a0[r], 0.f);
}

// ------------------------- K6: FFN2 + b2, x2, LN2 -> out (split-k x2) -------
__global__ void k_ffn2_ln(const float* __restrict__ W2, const float* __restrict__ b2,
                          const float* __restrict__ g2, const float* __restrict__ be2,
                          float* __restrict__ out) {
    int row0 = blockIdx.x * R2;
    int tid = threadIdx.x;  // 320
    int kh = (tid >= Hn) ? 1 : 0;
    int c = tid - kh * Hn;
    int lane = tid & 31, w = tid >> 5;
    __shared__ float hs[R2 * FFn];
    __shared__ float psum[R2][Hn];
    __shared__ float ys[R2][Hn];
    __shared__ float part1[5], part2[5];
    __shared__ float mu_s, rs_s;
    for (int q = tid; q < R2 * FFn; q += 320) hs[q] = dH1[row0 * FFn + q];
    __syncthreads();
    float acc[R2];
#pragma unroll
    for (int r = 0; r < R2; r++) acc[r] = kh ? 0.f : b2[c];
    int kbase = kh * 320;
    for (int k = 0; k < 320; k++) {
        float ww = W2[(kbase + k) * Hn + c];
#pragma unroll
        for (int r = 0; r < R2; r++) acc[r] += hs[r * FFn + kbase + k] * ww;
    }
    if (kh) {
#pragma unroll
        for (int r = 0; r < R2; r++) psum[r][c] = acc[r];
    }
    __syncthreads();
    if (!kh) {
#pragma unroll
        for (int r = 0; r < R2; r++) ys[r][c] = 2.f * (acc[r] + psum[r][c]);
    }
    __syncthreads();
    for (int r = 0; r < R2; r++) {
        float v = (tid < Hn) ? ys[r][c] : 0.f;
        float s1 = v, s2 = v * v;
#pragma unroll
        for (int off = 16; off; off >>= 1) {
            s1 += __shfl_xor_sync(0xffffffffu, s1, off);
            s2 += __shfl_xor_sync(0xffffffffu, s2, off);
        }
        if (lane == 0 && w < 5) { part1[w] = s1; part2[w] = s2; }
        __syncthreads();
        if (tid == 0) {
            float a = 0.f, q = 0.f;
#pragma unroll
            for (int t = 0; t < 5; t++) { a += part1[t]; q += part2[t]; }
            float mu = a / Hn;
            mu_s = mu;
            rs_s = rsqrtf(q / Hn - mu * mu + 1e-5f);
        }
        __syncthreads();
        if (tid < Hn) out[(row0 + r) * Hn + c] = (ys[r][c] - mu_s) * rs_s * g2[c] + be2[c];
        __syncthreads();
    }
}

// ------------------------- launch -------------------------------------------
extern "C" void kernel_launch(void* const* d_in, const int* in_sizes, int n_in,
                              void* d_out, int out_size) {
    const float* inp   = (const float*)d_in[0];
    const int* pos_s   = (const int*)d_in[1];
    const int* pos_e   = (const int*)d_in[2];
    const int* seq_len = (const int*)d_in[3];
    const int* lex     = (const int*)d_in[4];
    const float* pe_ss = (const float*)d_in[5];
    const float* pe_se = (const float*)d_in[6];
    const float* pe_es = (const float*)d_in[7];
    const float* pe_ee = (const float*)d_in[8];
    const float* W_fus = (const float*)d_in[9];
    const float* b_fus = (const float*)d_in[10];
    const float* Wq    = (const float*)d_in[11];
    const float* bq    = (const float*)d_in[12];
    const float* Wk    = (const float*)d_in[13];
    const float* bk    = (const float*)d_in[14];
    const float* Wv    = (const float*)d_in[15];
    const float* bv    = (const float*)d_in[16];
    const float* Wr    = (const float*)d_in[17];
    // d_in[18] = br: constant over j inside softmax -> cancels exactly, unused
    const float* u     = (const float*)d_in[19];
    const float* v     = (const float*)d_in[20];
    const float* W_fin = (const float*)d_in[21];
    const float* b_fin = (const float*)d_in[22];
    const float* ln1_g = (const float*)d_in[23];
    const float* ln1_b = (const float*)d_in[24];
    const float* W1    = (const float*)d_in[25];
    const float* b1    = (const float*)d_in[26];
    const float* W2    = (const float*)d_in[27];
    const float* b2    = (const float*)d_in[28];
    const float* ln2_g = (const float*)d_in[29];
    const float* ln2_b = (const float*)d_in[30];

    k_tables<<<4 * TBLOCKS, Hn>>>(pe_ss, pe_se, pe_es, pe_ee, W_fus, b_fus);  // 1
    k_qkvg<<<BSn / R2, Hn>>>(inp, Wq, bq, Wk, bk, Wv, bv, Wr, u, v);          // 2
    k_attn<<<BSn, 256>>>(pos_s, pos_e, seq_len, lex);                         // 3
    k_fin_ln<<<BSn / R2F, Hn>>>(W_fin, b_fin, ln1_g, ln1_b);                  // 4 (profiled)
    k_ffn1<<<(BSn / RF1) * 2, 320>>>(W1, b1);                                 // 5
    k_ffn2_ln<<<BSn / R2, 320>>>(W2, b2, ln2_g, ln2_b, (float*)d_out);        // 6
}

// round 7
// speedup vs baseline: 1.2314x; 1.0832x over previous
#include <cuda_runtime.h>
#include <cuda_fp16.h>

#define Bn 4
#define Sn 256
#define Hn 160
#define NHn 8
#define HDn 20
#define FFn 640
#define MAXLENn 512
#define TBLn 1025
#define BSn (Bn*Sn)
#define R2 8
#define TR 16
#define TBLOCKS 65     // ceil(1025/16)
#define RPAD 24        // uint4 per table row (20 data + 4 pad -> 384B, 128B aligned)
#define RSTR 80        // rel_s row stride in floats (320B: 16B-aligned, conflict-free)

// ------------------------- device scratch (static, no allocs) ----------------
__device__ uint4 dPT[4 * TBLn * RPAD];  // fused pe tables fp16, 384B padded rows
__device__ float dKT[Bn * Hn * Sn];     // K transposed: [b][hd][j]
__device__ float dV[BSn * Hn];
__device__ float dQU[BSn * Hn];         // q + u
__device__ float dG[BSn * NHn * Hn];    // g[b,i,h,c]
__device__ float dATT[BSn * Hn];
__device__ float dY1[BSn * Hn];
__device__ float dH1[BSn * FFn];

__device__ __forceinline__ void ffma2(unsigned long long& d, unsigned long long a,
                                      unsigned long long b) {
    asm("fma.rn.f32x2 %0, %1, %2, %3;" : "=l"(d) : "l"(a), "l"(b), "l"(d));
}
__device__ __forceinline__ __half2 u2h(unsigned x) {
    return *reinterpret_cast<__half2*>(&x);
}
__device__ __forceinline__ unsigned long long packf2(float2 f) {
    unsigned long long r;
    asm("mov.b64 %0, {%1,%2};" : "=l"(r) : "f"(f.x), "f"(f.y));
    return r;
}
__device__ __forceinline__ unsigned sum4relu(unsigned a, unsigned b, unsigned c,
                                             unsigned d, __half2 hz) {
    __half2 s = __hmax2(__hadd2(__hadd2(u2h(a), u2h(b)), __hadd2(u2h(c), u2h(d))), hz);
    return *reinterpret_cast<unsigned*>(&s);
}

// ------------------------- K1: P_t = pe_t @ W_fus[t] (+b_fus for t=0), fp16 out
// Two tables per launch so k_attn is the 4th launch overall.
__global__ void k_tables(const float* __restrict__ pe_a, const float* __restrict__ pe_b,
                         const float* __restrict__ W_fus, const float* __restrict__ b_fus,
                         int t0) {
    int sel = blockIdx.x / TBLOCKS;
    int t = t0 + sel;
    int r0 = (blockIdx.x % TBLOCKS) * TR;
    const float* pe = sel ? pe_b : pe_a;
    __shared__ float rows[TR][Hn];
    int c = threadIdx.x;
#pragma unroll
    for (int r = 0; r < TR; r++) {
        int rr = r0 + r;
        rows[r][c] = (rr < TBLn) ? pe[rr * Hn + c] : 0.f;
    }
    __syncthreads();
    float bias = (t == 0) ? b_fus[c] : 0.f;
    float acc[TR];
#pragma unroll
    for (int r = 0; r < TR; r++) acc[r] = bias;
    const float* wf = W_fus + t * Hn * Hn + c;
    for (int k0 = 0; k0 < Hn; k0 += 8) {
        float wb[8];
#pragma unroll
        for (int q = 0; q < 8; q++) wb[q] = wf[(k0 + q) * Hn];
#pragma unroll
        for (int q = 0; q < 8; q++)
#pragma unroll
            for (int r = 0; r < TR; r++) acc[r] += rows[r][k0 + q] * wb[q];
    }
    __half* out = (__half*)dPT;
#pragma unroll
    for (int r = 0; r < TR; r++) {
        int rr = r0 + r;
        if (rr < TBLn) out[(size_t)(t * TBLn + rr) * (RPAD * 8) + c] = __float2half(acc[r]);
    }
}

// ------------------------- K2: q/k/v projections + g ------------------------
__global__ void k_qkvg(const float* __restrict__ inp,
                       const float* __restrict__ Wq, const float* __restrict__ bq,
                       const float* __restrict__ Wk, const float* __restrict__ bk,
                       const float* __restrict__ Wv, const float* __restrict__ bv,
                       const float* __restrict__ Wr,
                       const float* __restrict__ u, const float* __restrict__ v) {
    int row0 = blockIdx.x * R2;
    int b = row0 >> 8;
    int i0 = row0 & 255;
    int c = threadIdx.x;
    __shared__ float xs[R2][Hn];
    __shared__ float qv[R2][Hn];
#pragma unroll
    for (int r = 0; r < R2; r++) xs[r][c] = inp[(row0 + r) * Hn + c];
    __syncthreads();

    float acc[R2];
    // ---- Q (batched loads, MLP=8)
#pragma unroll
    for (int r = 0; r < R2; r++) acc[r] = bq[c];
    {
        const float* wp = Wq + c;
        for (int k0 = 0; k0 < Hn; k0 += 8) {
            float wb[8];
#pragma unroll
            for (int q = 0; q < 8; q++) wb[q] = wp[(k0 + q) * Hn];
#pragma unroll
            for (int q = 0; q < 8; q++)
#pragma unroll
                for (int r = 0; r < R2; r++) acc[r] += xs[r][k0 + q] * wb[q];
        }
    }
    {
        float uu = u[c], vv = v[c];
#pragma unroll
        for (int r = 0; r < R2; r++) {
            dQU[(row0 + r) * Hn + c] = acc[r] + uu;
            qv[r][c] = acc[r] + vv;
        }
    }
    // ---- K -> transposed store
#pragma unroll
    for (int r = 0; r < R2; r++) acc[r] = bk[c];
    {
        const float* wp = Wk + c;
        for (int k0 = 0; k0 < Hn; k0 += 8) {
            float wb[8];
#pragma unroll
            for (int q = 0; q < 8; q++) wb[q] = wp[(k0 + q) * Hn];
#pragma unroll
            for (int q = 0; q < 8; q++)
#pragma unroll
                for (int r = 0; r < R2; r++) acc[r] += xs[r][k0 + q] * wb[q];
        }
    }
#pragma unroll
    for (int r = 0; r < R2; r++) dKT[((size_t)b * Hn + c) * Sn + (i0 + r)] = acc[r];
    // ---- V
#pragma unroll
    for (int r = 0; r < R2; r++) acc[r] = bv[c];
    {
        const float* wp = Wv + c;
        for (int k0 = 0; k0 < Hn; k0 += 8) {
            float wb[8];
#pragma unroll
            for (int q = 0; q < 8; q++) wb[q] = wp[(k0 + q) * Hn];
#pragma unroll
            for (int q = 0; q < 8; q++)
#pragma unroll
                for (int r = 0; r < R2; r++) acc[r] += xs[r][k0 + q] * wb[q];
        }
    }
#pragma unroll
    for (int r = 0; r < R2; r++) dV[(row0 + r) * Hn + c] = acc[r];
    __syncthreads();

    // ---- g: row c of Wr is contiguous; float4 loads give MLP
    const float4* wr4 = reinterpret_cast<const float4*>(Wr + (size_t)c * Hn);
    for (int h = 0; h < NHn; h++) {
        float a2[R2];
#pragma unroll
        for (int r = 0; r < R2; r++) a2[r] = 0.f;
        float4 wv4[5];
#pragma unroll
        for (int d4 = 0; d4 < 5; d4++) wv4[d4] = wr4[h * 5 + d4];
#pragma unroll
        for (int d4 = 0; d4 < 5; d4++) {
            int hd = h * HDn + d4 * 4;
#pragma unroll
            for (int r = 0; r < R2; r++) {
                a2[r] += qv[r][hd + 0] * wv4[d4].x + qv[r][hd + 1] * wv4[d4].y +
                         qv[r][hd + 2] * wv4[d4].z + qv[r][hd + 3] * wv4[d4].w;
            }
        }
#pragma unroll
        for (int r = 0; r < R2; r++) dG[((size_t)(row0 + r) * NHn + h) * Hn + c] = a2[r];
    }
}

// ------------------------- K3: fused A_C + staged B_D + softmax + attn@V ----
__global__ void __launch_bounds__(256, 2) k_attn(const int* __restrict__ pos_s,
                                                 const int* __restrict__ pos_e,
                                                 const int* __restrict__ seq_len,
                                                 const int* __restrict__ lex) {
    int b = blockIdx.x >> 8;
    int i = blockIdx.x & 255;
    int tid = threadIdx.x;
    int lane = tid & 31;
    int w = tid >> 5;

    __shared__ float sc[NHn][257];
    __shared__ int pssO[Sn], pesO[Sn];    // pos * RPAD (uint4 units)
    __shared__ float quv[Hn];
    __shared__ __align__(16) float g_s[NHn * Hn];
    __shared__ float rinv[NHn];
    __shared__ __align__(16) float rel_s[64 * RSTR];  // fp16 rel rows
    __shared__ int psi_s, pei_s, lim_s;

    {
        int ps = pos_s[b * Sn + tid];
        int pe = pos_e[b * Sn + tid];
        pssO[tid] = ps * RPAD;
        pesO[tid] = pe * RPAD;
        if (tid == i) { psi_s = ps; pei_s = pe; }
        if (tid == 0) lim_s = seq_len[b] + lex[0];
    }
    if (tid < Hn) quv[tid] = dQU[(size_t)(b * Sn + i) * Hn + tid];
    {
        const float* gp = dG + (size_t)(b * Sn + i) * NHn * Hn;
        for (int t = tid; t < NHn * Hn; t += 256) g_s[t] = gp[t];
    }
    __syncthreads();

    int lim = lim_s;

    // ---- Phase AC (unscaled); invalid j get -1e15
    if (tid < lim) {
        float acc[NHn];
#pragma unroll
        for (int h = 0; h < NHn; h++) acc[h] = 0.f;
#pragma unroll
        for (int h = 0; h < NHn; h++) {
            const float* kp = dKT + ((size_t)b * Hn + h * HDn) * Sn + tid;
#pragma unroll
            for (int d = 0; d < HDn; d++) acc[h] += quv[h * HDn + d] * kp[(size_t)d * Sn];
        }
#pragma unroll
        for (int h = 0; h < NHn; h++) sc[h][tid] = acc[h];
    } else {
#pragma unroll
        for (int h = 0; h < NHn; h++) sc[h][tid] = -1e15f;
    }

    // ---- Phase BD: 4 chunks of 64 j; stage fp16 rel in smem, then 4-lane dot
    const uint4* base0 = dPT + (size_t)(0 * TBLn + psi_s + MAXLENn) * RPAD;
    const uint4* base1 = dPT + (size_t)(1 * TBLn + psi_s + MAXLENn) * RPAD;
    const uint4* base2 = dPT + (size_t)(2 * TBLn + pei_s + MAXLENn) * RPAD;
    const uint4* base3 = dPT + (size_t)(3 * TBLn + pei_s + MAXLENn) * RPAD;
    const __half2 hz = __float2half2_rn(0.f);
    int slot3 = tid >> 3;     // 0..31
    int l8 = tid & 7;
    int grp = lane >> 2;      // 0..7
    int l4 = lane & 3;
    const float scale = 0.223606797749979f;  // 1/sqrt(20)

#pragma unroll 1
    for (int chunk = 0; chunk < 4; chunk++) {
        int j0 = chunk * 64;
        __syncthreads();  // previous chunk's compute reads done
        // stage: 8 lanes per j, 2 passes of 32 j
#pragma unroll
        for (int p = 0; p < 2; p++) {
            int jj = slot3 + p * 32;
            int j = j0 + jj;
            if (j < lim) {
                int oS = pssO[j], oE = pesO[j];
                const uint4* r0 = base0 - oS;
                const uint4* r1 = base1 - oE;
                const uint4* r2 = base2 - oS;
                const uint4* r3 = base3 - oE;
#pragma unroll
                for (int m = 0; m < 3; m++) {
                    int k = l8 + 8 * m;
                    if (k < 20) {
                        uint4 a0 = r0[k], a1 = r1[k], a2 = r2[k], a3 = r3[k];
                        uint4 o;
                        o.x = sum4relu(a0.x, a1.x, a2.x, a3.x, hz);
                        o.y = sum4relu(a0.y, a1.y, a2.y, a3.y, hz);
                        o.z = sum4relu(a0.z, a1.z, a2.z, a3.z, hz);
                        o.w = sum4relu(a0.w, a1.w, a2.w, a3.w, hz);
                        *reinterpret_cast<uint4*>(rel_s + jj * RSTR + k * 4) = o;
                    }
                }
            }
        }
        __syncthreads();
        // compute: warp w handles j = j0 + w*8 + grp; lane l4 covers gi = l4+4m
        int jj = w * 8 + grp;
        int j = j0 + jj;
        unsigned long long acc2[NHn];
#pragma unroll
        for (int h = 0; h < NHn; h++) acc2[h] = 0ull;
        const float* rb = rel_s + jj * RSTR;
#pragma unroll
        for (int m = 0; m < 5; m++) {
            int k = l4 + 4 * m;
            uint4 rv = *reinterpret_cast<const uint4*>(rb + k * 4);
            unsigned long long rel01 = packf2(__half22float2(u2h(rv.x)));
            unsigned long long rel23 = packf2(__half22float2(u2h(rv.y)));
            unsigned long long rel45 = packf2(__half22float2(u2h(rv.z)));
            unsigned long long rel67 = packf2(__half22float2(u2h(rv.w)));
#pragma unroll
            for (int h = 0; h < NHn; h++) {
                const ulonglong2* gg =
                    reinterpret_cast<const ulonglong2*>(g_s + h * Hn + k * 8);
                ulonglong2 gA = gg[0];
                ulonglong2 gB = gg[1];
                ffma2(acc2[h], rel01, gA.x);
                ffma2(acc2[h], rel23, gA.y);
                ffma2(acc2[h], rel45, gB.x);
                ffma2(acc2[h], rel67, gB.y);
            }
        }
        float a[NHn];
#pragma unroll
        for (int h = 0; h < NHn; h++) {
            float lo, hi;
            asm("mov.b64 {%0,%1}, %2;" : "=f"(lo), "=f"(hi) : "l"(acc2[h]));
            a[h] = lo + hi;
        }
        // reduce-scatter over 4-lane group: lane l4 ends with heads {hbase, hbase+1}
        {
            bool hb = l4 & 1;
#pragma unroll
            for (int k2 = 0; k2 < 4; k2++) {
                float send = hb ? a[k2] : a[k2 + 4];
                float got = __shfl_xor_sync(0xffffffffu, send, 1);
                a[k2] = (hb ? a[k2 + 4] : a[k2]) + got;
            }
        }
        {
            bool hb = l4 & 2;
#pragma unroll
            for (int k2 = 0; k2 < 2; k2++) {
                float send = hb ? a[k2] : a[k2 + 2];
                float got = __shfl_xor_sync(0xffffffffu, send, 2);
                a[k2] = (hb ? a[k2 + 2] : a[k2]) + got;
            }
        }
        if (j < lim) {
            int hbase = (l4 & 1) * 4 + (l4 & 2);
            sc[hbase][j] += a[0];
            sc[hbase + 1][j] += a[1];
        }
    }
    __syncthreads();

    // ---- scale + mask
    {
        bool valid = tid < lim;
#pragma unroll
        for (int h = 0; h < NHn; h++) {
            float sv = sc[h][tid] * scale;
            sc[h][tid] = valid ? sv : -1e15f;
        }
    }
    __syncthreads();

    // ---- per-head softmax (warp w = head w); unnormalized p + 1/sum
    {
        int h = w;
        float m = -1e30f;
#pragma unroll
        for (int q = 0; q < 8; q++) m = fmaxf(m, sc[h][lane + q * 32]);
#pragma unroll
        for (int off = 16; off; off >>= 1) m = fmaxf(m, __shfl_xor_sync(0xffffffffu, m, off));
        float ssum = 0.f;
#pragma unroll
        for (int q = 0; q < 8; q++) {
            float p = __expf(sc[h][lane + q * 32] - m);
            sc[h][lane + q * 32] = p;
            ssum += p;
        }
#pragma unroll
        for (int off = 16; off; off >>= 1) ssum += __shfl_xor_sync(0xffffffffu, ssum, off);
        if (lane == 0) rinv[h] = 1.0f / ssum;
    }
    __syncthreads();

    // ---- out[c] = (sum_j p[h][j] * V[b,j,c]) * rinv[h]
    if (tid < Hn) {
        int c = tid;
        int h = c / HDn;
        const float* vp = dV + (size_t)b * Sn * Hn + c;
        float acc = 0.f;
#pragma unroll 8
        for (int j = 0; j < Sn; j++) acc += sc[h][j] * vp[(size_t)j * Hn];
        dATT[((size_t)b * Sn + i) * Hn + c] = acc * rinv[h];
    }
}

// ------------------------- K4: @W_fin + b_fin, x2, LN1 (R2=8, batched) ------
__global__ void k_fin_ln(const float* __restrict__ W_fin, const float* __restrict__ b_fin,
                         const float* __restrict__ g1, const float* __restrict__ be1) {
    int row0 = blockIdx.x * R2;
    int c = threadIdx.x;
    int lane = c & 31, w = c >> 5;
    __shared__ float xs[R2][Hn];
    __shared__ float ys[R2][Hn];
    __shared__ float part1[5], part2[5];
    __shared__ float mu_s, rs_s;
#pragma unroll
    for (int r = 0; r < R2; r++) xs[r][c] = dATT[(row0 + r) * Hn + c];
    __syncthreads();
    float acc[R2];
#pragma unroll
    for (int r = 0; r < R2; r++) acc[r] = b_fin[c];
    {
        const float* wp = W_fin + c;
        for (int k0 = 0; k0 < Hn; k0 += 8) {
            float wb[8];
#pragma unroll
            for (int q = 0; q < 8; q++) wb[q] = wp[(k0 + q) * Hn];
#pragma unroll
            for (int q = 0; q < 8; q++)
#pragma unroll
                for (int r = 0; r < R2; r++) acc[r] += xs[r][k0 + q] * wb[q];
        }
    }
#pragma unroll
    for (int r = 0; r < R2; r++) ys[r][c] = 2.f * acc[r];
    __syncthreads();
    for (int r = 0; r < R2; r++) {
        float v = ys[r][c];
        float s1 = v, s2 = v * v;
#pragma unroll
        for (int off = 16; off; off >>= 1) {
            s1 += __shfl_xor_sync(0xffffffffu, s1, off);
            s2 += __shfl_xor_sync(0xffffffffu, s2, off);
        }
        if (lane == 0) { part1[w] = s1; part2[w] = s2; }
        __syncthreads();
        if (c == 0) {
            float a = 0.f, q = 0.f;
#pragma unroll
            for (int t = 0; t < 5; t++) { a += part1[t]; q += part2[t]; }
            float mu = a / Hn;
            mu_s = mu;
            rs_s = rsqrtf(q / Hn - mu * mu + 1e-5f);
        }
        __syncthreads();
        dY1[(row0 + r) * Hn + c] = (v - mu_s) * rs_s * g1[c] + be1[c];
        __syncthreads();
    }
}

// ------------------------- K5: FFN1 = relu(y1 @ W1 + b1), 16-row x col-half --
#define RF1 16
__global__ void k_ffn1(const float* __restrict__ W1, const float* __restrict__ b1) {
    int rb = blockIdx.x >> 1;
    int half = blockIdx.x & 1;
    int row0 = rb * RF1;
    int t = threadIdx.x;  // 320
    int c = half * 320 + t;
    __shared__ float xs[RF1 * Hn];
    for (int q = t; q < RF1 * Hn; q += 320) xs[q] = dY1[row0 * Hn + q];
    __syncthreads();
    float a0[RF1];
#pragma unroll
    for (int r = 0; r < RF1; r++) a0[r] = b1[c];
    {
        const float* wp = W1 + c;
        for (int k0 = 0; k0 < Hn; k0 += 8) {
            float wb[8];
#pragma unroll
            for (int q = 0; q < 8; q++) wb[q] = wp[(k0 + q) * FFn];
#pragma unroll
            for (int q = 0; q < 8; q++)
#pragma unroll
                for (int r = 0; r < RF1; r++) a0[r] += xs[r * Hn + k0 + q] * wb[q];
        }
    }
#pragma unroll
    for (int r = 0; r < RF1; r++) dH1[(row0 + r) * FFn + c] = fmaxf(a0[r], 0.f);
}

// ------------------------- K6: FFN2 + b2, x2, LN2 -> out (split-k x2) -------
__global__ void k_ffn2_ln(const float* __restrict__ W2, const float* __restrict__ b2,
                          const float* __restrict__ g2, const float* __restrict__ be2,
                          float* __restrict__ out) {
    int row0 = blockIdx.x * R2;
    int tid = threadIdx.x;  // 320
    int kh = (tid >= Hn) ? 1 : 0;
    int c = tid - kh * Hn;
    int lane = tid & 31, w = tid >> 5;
    __shared__ float hs[R2 * FFn];
    __shared__ float psum[R2][Hn];
    __shared__ float ys[R2][Hn];
    __shared__ float part1[5], part2[5];
    __shared__ float mu_s, rs_s;
    for (int q = tid; q < R2 * FFn; q += 320) hs[q] = dH1[row0 * FFn + q];
    __syncthreads();
    float acc[R2];
#pragma unroll
    for (int r = 0; r < R2; r++) acc[r] = kh ? 0.f : b2[c];
    int kbase = kh * 320;
    {
        const float* wp = W2 + (size_t)kbase * Hn + c;
        for (int k0 = 0; k0 < 320; k0 += 8) {
            float wb[8];
#pragma unroll
            for (int q = 0; q < 8; q++) wb[q] = wp[(k0 + q) * Hn];
#pragma unroll
            for (int q = 0; q < 8; q++)
#pragma unroll
                for (int r = 0; r < R2; r++) acc[r] += hs[r * FFn + kbase + k0 + q] * wb[q];
        }
    }
    if (kh) {
#pragma unroll
        for (int r = 0; r < R2; r++) psum[r][c] = acc[r];
    }
    __syncthreads();
    if (!kh) {
#pragma unroll
        for (int r = 0; r < R2; r++) ys[r][c] = 2.f * (acc[r] + psum[r][c]);
    }
    __syncthreads();
    for (int r = 0; r < R2; r++) {
        float v = (tid < Hn) ? ys[r][c] : 0.f;
        float s1 = v, s2 = v * v;
#pragma unroll
        for (int off = 16; off; off >>= 1) {
            s1 += __shfl_xor_sync(0xffffffffu, s1, off);
            s2 += __shfl_xor_sync(0xffffffffu, s2, off);
        }
        if (lane == 0 && w < 5) { part1[w] = s1; part2[w] = s2; }
        __syncthreads();
        if (tid == 0) {
            float a = 0.f, q = 0.f;
#pragma unroll
            for (int t = 0; t < 5; t++) { a += part1[t]; q += part2[t]; }
            float mu = a / Hn;
            mu_s = mu;
            rs_s = rsqrtf(q / Hn - mu * mu + 1e-5f);
        }
        __syncthreads();
        if (tid < Hn) out[(row0 + r) * Hn + c] = (ys[r][c] - mu_s) * rs_s * g2[c] + be2[c];
        __syncthreads();
    }
}

// ------------------------- launch -------------------------------------------
extern "C" void kernel_launch(void* const* d_in, const int* in_sizes, int n_in,
                              void* d_out, int out_size) {
    const float* inp   = (const float*)d_in[0];
    const int* pos_s   = (const int*)d_in[1];
    const int* pos_e   = (const int*)d_in[2];
    const int* seq_len = (const int*)d_in[3];
    const int* lex     = (const int*)d_in[4];
    const float* pe_ss = (const float*)d_in[5];
    const float* pe_se = (const float*)d_in[6];
    const float* pe_es = (const float*)d_in[7];
    const float* pe_ee = (const float*)d_in[8];
    const float* W_fus = (const float*)d_in[9];
    const float* b_fus = (const float*)d_in[10];
    const float* Wq    = (const float*)d_in[11];
    const float* bq    = (const float*)d_in[12];
    const float* Wk    = (const float*)d_in[13];
    const float* bk    = (const float*)d_in[14];
    const float* Wv    = (const float*)d_in[15];
    const float* bv    = (const float*)d_in[16];
    const float* Wr    = (const float*)d_in[17];
    // d_in[18] = br: constant over j inside softmax -> cancels exactly, unused
    const float* u     = (const float*)d_in[19];
    const float* v     = (const float*)d_in[20];
    const float* W_fin = (const float*)d_in[21];
    const float* b_fin = (const float*)d_in[22];
    const float* ln1_g = (const float*)d_in[23];
    const float* ln1_b = (const float*)d_in[24];
    const float* W1    = (const float*)d_in[25];
    const float* b1    = (const float*)d_in[26];
    const float* W2    = (const float*)d_in[27];
    const float* b2    = (const float*)d_in[28];
    const float* ln2_g = (const float*)d_in[29];
    const float* ln2_b = (const float*)d_in[30];

    k_tables<<<2 * TBLOCKS, Hn>>>(pe_ss, pe_se, W_fus, b_fus, 0);     // 1
    k_tables<<<2 * TBLOCKS, Hn>>>(pe_es, pe_ee, W_fus, b_fus, 2);     // 2
    k_qkvg<<<BSn / R2, Hn>>>(inp, Wq, bq, Wk, bk, Wv, bv, Wr, u, v);  // 3
    k_attn<<<BSn, 256>>>(pos_s, pos_e, seq_len, lex);                 // 4 (profiled)
    k_fin_ln<<<BSn / R2, Hn>>>(W_fin, b_fin, ln1_g, ln1_b);           // 5
    k_ffn1<<<(BSn / RF1) * 2, 320>>>(W1, b1);                         // 6
    k_ffn2_ln<<<BSn / R2, 320>>>(W2, b2, ln2_g, ln2_b, (float*)d_out);// 7
}